// round 15
// baseline (speedup 1.0000x reference)
#include <cuda_runtime.h>
#include <cuda_fp16.h>
#include <math.h>

#define NB    256
#define TP    32
#define TFUT  256
#define HH    100
#define NF    275
#define HGG   75
#define HOO   75
#define NTHR  288
#define NCTA  256

// ---- packed weights in global scratch ----
// g_W1H[kp*275+n] = half2(W1[n][2kp], W1[n][2kp+1]), kp 0..50 (k=101 pad 0)
__device__ __align__(16) unsigned int g_W1H[14028];
// g_W3H[kp*100+n] = half2(W3[n][2kp], W3[n][2kp+1]), kp 0..137 (k=275 pad 0)
__device__ __align__(16) unsigned int g_W3H[13800];
// g_W2H[k*138+j] = half2(W2[2j][k], W2[2j+1][k]), k 0..275 (row 275 / col 275 pad 0)
__device__ __align__(16) __half2 g_W2H[276 * 138];
__device__ __align__(16) float g_WhhT[100 * 300];
__device__ __align__(16) float g_oW1T[100 * 75];
__device__ __align__(16) float g_oW2T[75 * 75];
__device__ float g_hB[NB * HH];
__device__ float g_gx[NB * 2];
__device__ float g_z0[NB * HH];

// ---- shared layout (4B units), total 28584*4 = 114,336 B (2 CTAs/SM fit) ----
#define OFF_W1H 0        // 14028 uints
#define OFF_W3H 14028    // 13800 uints
#define BUF_IN  27828    // float[104]  (101..103 pad)
#define BUF_HA  27932    // float[276]  (shared HID/A2 buffer, slot 275 pad)
#define BUF_Y   28208    // float[100]
#define BUF_P   28308    // float[276]  (partials / GRU u / outmlp o2)
#define SMEM_FLOATS 28584
#define SMEM_BYTES (SMEM_FLOATS * 4)

__device__ __forceinline__ float leaky1(float x) {
    const float SL = 1.0f / 5.5f;
    return x >= 0.f ? x : x * SL;
}
__device__ __forceinline__ float sigm1(float x) { return 1.f / (1.f + expf(-x)); }

// ---- W2 ring macros: 16-row chunks, scalar x, 2 outputs/thread, 4 chains ----
#define W2R16(R, ROW0) {                                                      \
    _Pragma("unroll")                                                         \
    for (int i_ = 0; i_ < 16; i_++)                                           \
        R[i_] = __ldcg((const unsigned int*)(ph + ((ROW0) + i_) * 138)); }

#define W2C16(R, OFF) {                                                       \
    _Pragma("unroll")                                                         \
    for (int i_ = 0; i_ < 16; i_++) {                                         \
        float2 wf_ = __half22float2(*(const __half2*)&R[i_]);                 \
        float xv_ = xs[(OFF) + i_];                                           \
        if (i_ & 1) { c2 = fmaf(wf_.x, xv_, c2); c3 = fmaf(wf_.y, xv_, c3); } \
        else        { c0 = fmaf(wf_.x, xv_, c0); c1 = fmaf(wf_.y, xv_, c1); } \
    } }

// ---- one RK4 stage, single batch row, 288 threads ----
__device__ __forceinline__ void field_stage(int tid, float* sm, int stage,
        float dt, float tnext, bool write_in, float& rks,
        float rb1, float rb2a, float rb2b, float rb3) {
    float* s_in = sm + BUF_IN;
    float* ha   = sm + BUF_HA;
    float* s_y  = sm + BUF_Y;
    float* P    = sm + BUF_P;

    int q = (tid >= 138) ? 1 : 0;
    int j = tid - q * 138;
    bool act2 = (tid < 276);
    const __half2* ph = g_W2H + (q * 138) * 138 + j;

    // W2 prefetch: slice rows 0..31 + tail 128..137, issued before L1
    unsigned int A[16], B[16], T[10];
    if (act2) {
        W2R16(A, 0)
        W2R16(B, 16)
#pragma unroll
        for (int i = 0; i < 10; i++)
            T[i] = __ldcg((const unsigned int*)(ph + (128 + i) * 138));
    }

    // ---- L1: 101 -> 275, fp16 W1 in smem ----
    if (tid < NF) {
        const unsigned int* w1 = ((const unsigned int*)(sm + OFF_W1H)) + tid;
        const float2* x2 = (const float2*)s_in;
        float a0 = 0.f, a1 = 0.f, b0 = 0.f, b1 = 0.f;
#pragma unroll
        for (int kp = 0; kp < 50; kp += 2) {
            unsigned int wu0 = w1[kp * 275], wu1 = w1[(kp + 1) * 275];
            float2 w0 = __half22float2(*(const __half2*)&wu0);
            float2 w1f = __half22float2(*(const __half2*)&wu1);
            float2 xA = x2[kp], xB = x2[kp + 1];
            a0 = fmaf(w0.x, xA.x, a0);  a1 = fmaf(w0.y, xA.y, a1);
            b0 = fmaf(w1f.x, xB.x, b0); b1 = fmaf(w1f.y, xB.y, b1);
        }
        {   // kp = 50 (k=100, k=101 pad)
            unsigned int wu = w1[50 * 275];
            float2 w = __half22float2(*(const __half2*)&wu);
            float2 xA = x2[50];
            a0 = fmaf(w.x, xA.x, a0); a1 = fmaf(w.y, xA.y, a1);
        }
        ha[tid] = tanhf((a0 + a1) + (b0 + b1) + rb1);
    }
    __syncthreads();

    // ---- L2: 275 -> 275, fp16 W2 streamed, 2-way k-split, 2 outputs/thread ----
    float accA = 0.f, accB = 0.f;
    if (act2) {
        const float* xs = ha + q * 138;
        float c0 = 0.f, c1 = 0.f, c2 = 0.f, c3 = 0.f;
        W2C16(A, 0)   W2R16(A, 32)
        W2C16(B, 16)  W2R16(B, 48)
        W2C16(A, 32)  W2R16(A, 64)
        W2C16(B, 48)  W2R16(B, 80)
        W2C16(A, 64)  W2R16(A, 96)
        W2C16(B, 80)  W2R16(B, 112)
        W2C16(A, 96)
        W2C16(B, 112)
#pragma unroll
        for (int i = 0; i < 10; i++) {   // tail rows 128..137
            float2 wf = __half22float2(*(const __half2*)&T[i]);
            float xv = xs[128 + i];
            if (i & 1) { c2 = fmaf(wf.x, xv, c2); c3 = fmaf(wf.y, xv, c3); }
            else       { c0 = fmaf(wf.x, xv, c0); c1 = fmaf(wf.y, xv, c1); }
        }
        accA = c0 + c2; accB = c1 + c3;
        if (q) ((float2*)P)[j] = make_float2(accA, accB);
    }
    __syncthreads();
    if (tid < 138) {
        float2 p = ((float2*)P)[tid];
        ha[2 * tid]     = tanhf(accA + p.x + rb2a);
        ha[2 * tid + 1] = tanhf(accB + p.y + rb2b);
    }
    __syncthreads();

    // ---- L3: 275 -> 100, fp16 W3 in smem, 2-way k-split (69 pairs each) ----
    float l3 = 0.f;
    if (tid < 200) {
        int q3 = (tid >= 100) ? 1 : 0;
        int n3 = tid - q3 * 100;
        const unsigned int* w3 = ((const unsigned int*)(sm + OFF_W3H)) + n3;
        const float2* x2 = (const float2*)ha;
        int kp0 = q3 * 69;
        float a0 = 0.f, a1 = 0.f, b0 = 0.f, b1 = 0.f;
#pragma unroll
        for (int u = 0; u < 68; u += 2) {
            unsigned int wu0 = w3[(kp0 + u) * 100];
            unsigned int wu1 = w3[(kp0 + u + 1) * 100];
            float2 w0 = __half22float2(*(const __half2*)&wu0);
            float2 w1f = __half22float2(*(const __half2*)&wu1);
            float2 xA = x2[kp0 + u], xB = x2[kp0 + u + 1];
            a0 = fmaf(w0.x, xA.x, a0);  a1 = fmaf(w0.y, xA.y, a1);
            b0 = fmaf(w1f.x, xB.x, b0); b1 = fmaf(w1f.y, xB.y, b1);
        }
        {   // pair kp0+68
            unsigned int wu = w3[(kp0 + 68) * 100];
            float2 w = __half22float2(*(const __half2*)&wu);
            float2 xA = x2[kp0 + 68];
            a0 = fmaf(w.x, xA.x, a0); a1 = fmaf(w.y, xA.y, a1);
        }
        l3 = (a0 + a1) + (b0 + b1);
        if (q3) P[n3] = l3;
    }
    __syncthreads();
    if (tid < 100) {
        float f = tanhf(l3 + P[tid] + rb3);
        float y = s_y[tid];
        if (stage == 0) {
            rks = f;
            s_in[1 + tid] = fmaf(0.5f * dt, f, y);
        } else if (stage == 1) {
            rks += 2.f * f;
            s_in[1 + tid] = fmaf(0.5f * dt, f, y);
        } else if (stage == 2) {
            rks += 2.f * f;
            s_in[1 + tid] = fmaf(dt, f, y);
        } else {
            float yn = y + dt * (rks + f) / 6.f;
            s_y[tid] = yn;
            if (write_in) s_in[1 + tid] = yn;
        }
        if (tid == 0 && (stage < 3 || write_in)) s_in[0] = tnext;
    }
    __syncthreads();
}

// ---- RK4, NSUB=2, single row ----
__device__ __forceinline__ void integrate2(int tid, float* sm, float t0, float t1,
        float rb1, float rb2a, float rb2b, float rb3) {
    float* s_in = sm + BUF_IN;
    float* s_y  = sm + BUF_Y;
    float dt = (t1 - t0) * 0.5f;
    if (tid < HH) s_in[1 + tid] = s_y[tid];
    if (tid == 0) s_in[0] = t0;
    __syncthreads();
    float rks = 0.f;
#pragma unroll 1
    for (int st = 0; st < 8; st++) {
        int stage = st & 3, sub = st >> 2;
        float tb = t0 + sub * dt;
        float tnext = (stage <= 1) ? tb + 0.5f * dt : tb + dt;
        field_stage(tid, sm, stage, dt, tnext, (st == 3), rks,
                    rb1, rb2a, rb2b, rb3);
    }
}

// ---- shared init ----
__device__ __forceinline__ void load_shared_weights(int tid, float* sm) {
    const uint4* s1 = (const uint4*)g_W1H;
    uint4* d1 = (uint4*)sm;
    for (int i = tid; i < 14028 / 4; i += NTHR) d1[i] = s1[i];
    const uint4* s2 = (const uint4*)g_W3H;
    uint4* d2 = (uint4*)(sm + OFF_W3H);
    for (int i = tid; i < 13800 / 4; i += NTHR) d2[i] = s2[i];
    if (tid == 0) {
        sm[BUF_IN + 101] = sm[BUF_IN + 102] = sm[BUF_IN + 103] = 0.f;
        sm[BUF_HA + 275] = 0.f;
    }
}

// ---- prep: build packed weight copies ----
__global__ void prep_kernel(const float* __restrict__ fW1, const float* __restrict__ fW2,
                            const float* __restrict__ fW3, const float* __restrict__ Whh,
                            const float* __restrict__ oW1, const float* __restrict__ oW2) {
    for (int i = blockIdx.x * blockDim.x + threadIdx.x; i < 109041;
         i += gridDim.x * blockDim.x) {
        if (i < 14028) {
            int kp = i / 275, n = i % 275;
            float v0 = 0.f, v1 = 0.f;
            if (kp < 51) {
                int k0 = 2 * kp, k1 = 2 * kp + 1;
                v0 = fW1[n * 101 + k0];
                v1 = (k1 < 101) ? fW1[n * 101 + k1] : 0.f;
            }
            __half2 hv = __floats2half2_rn(v0, v1);
            g_W1H[i] = *(unsigned int*)&hv;
        } else if (i < 27828) {
            int idx = i - 14028;
            int kp = idx / 100, n = idx % 100;
            int k0 = 2 * kp, k1 = 2 * kp + 1;
            float v0 = fW3[n * 275 + k0];
            float v1 = (k1 < 275) ? fW3[n * 275 + k1] : 0.f;
            __half2 hv = __floats2half2_rn(v0, v1);
            g_W3H[idx] = *(unsigned int*)&hv;
        } else if (i < 65916) {
            int idx = i - 27828;
            int k = idx / 138, jj = idx % 138;
            int n0 = 2 * jj, n1 = 2 * jj + 1;
            float v0 = (k < 275) ? fW2[n0 * 275 + k] : 0.f;
            float v1 = (k < 275 && n1 < 275) ? fW2[n1 * 275 + k] : 0.f;
            g_W2H[idx] = __floats2half2_rn(v0, v1);
        } else if (i < 95916) {
            int jj = i - 65916, k = jj / 300, n = jj % 300;
            g_WhhT[jj] = Whh[n * 100 + k];
        } else if (i < 103416) {
            int jj = i - 95916, k = jj / 75, n = jj % 75;
            g_oW1T[jj] = oW1[n * 100 + k];
        } else {
            int jj = i - 103416, k = jj / 75, n = jj % 75;
            g_oW2T[jj] = oW2[n * 75 + k];
        }
    }
}

// ---- encode: 256 CTAs, one row each ----
__global__ void __launch_bounds__(NTHR, 2) encode_kernel(
        const float* __restrict__ past, const float* __restrict__ h0,
        const float* __restrict__ fb1, const float* __restrict__ fb2,
        const float* __restrict__ fb3,
        const float* __restrict__ Wih, const float* __restrict__ bih,
        const float* __restrict__ bhh) {
    extern __shared__ float sm[];
    int tid = threadIdx.x;
    int r = blockIdx.x;

    load_shared_weights(tid, sm);

    float rb1 = (tid < NF) ? __ldg(fb1 + tid) : 0.f;
    float rb2a = 0.f, rb2b = 0.f;
    if (tid < 138) {
        rb2a = __ldg(fb2 + 2 * tid);
        rb2b = (2 * tid + 1 < NF) ? __ldg(fb2 + 2 * tid + 1) : 0.f;
    }
    float rb3 = (tid < HH) ? __ldg(fb3 + tid) : 0.f;

    float* s_y   = sm + BUF_Y;
    float* s_u   = sm + BUF_P;          // [200]
    float* s_inn = sm + BUF_HA;         // [100]
    float* s_hn  = sm + BUF_HA + 100;   // [100]
    if (tid < HH) s_y[tid] = h0[r * HH + tid];
    __syncthreads();

    float tprev = 0.f;
    for (int step = 0; step < TP; step++) {
        float tcur = past[(r * TP + step) * 2];
        float t0 = (step == 0) ? tcur - 1.f : tprev;
        integrate2(tid, sm, t0, tcur, rb1, rb2a, rb2b, rb3);

        float x = past[(r * TP + step) * 2 + 1];
        const float4* y4 = (const float4*)s_y;
        for (int jj = tid; jj < 300; jj += NTHR) {
            float bh = __ldg(bhh + jj);
            float a0 = bh, a1 = 0.f, b0 = 0.f, b1 = 0.f;
#pragma unroll
            for (int k = 0; k < 100; k += 4) {
                float w0 = __ldcg(g_WhhT + k * 300 + jj);
                float w1 = __ldcg(g_WhhT + (k + 1) * 300 + jj);
                float w2 = __ldcg(g_WhhT + (k + 2) * 300 + jj);
                float w3 = __ldcg(g_WhhT + (k + 3) * 300 + jj);
                float4 y = y4[k >> 2];
                a0 = fmaf(w0, y.x, a0); a1 = fmaf(w1, y.y, a1);
                b0 = fmaf(w2, y.z, b0); b1 = fmaf(w3, y.w, b1);
            }
            float a = (a0 + a1) + (b0 + b1);
            float gi = fmaf(__ldg(Wih + jj), x, __ldg(bih + jj));
            if (jj < 200) s_u[jj] = gi + a;
            else { s_inn[jj - 200] = gi; s_hn[jj - 200] = a; }
        }
        __syncthreads();
        if (tid < HH) {
            float rr = sigm1(s_u[tid]);
            float zz = sigm1(s_u[HH + tid]);
            float nn = tanhf(s_inn[tid] + rr * s_hn[tid]);
            s_y[tid] = (1.f - zz) * nn + zz * s_y[tid];
        }
        __syncthreads();
        tprev = tcur;
    }
    if (tid < HH) g_hB[r * HH + tid] = s_y[tid];
}

// ---- decoder head ----
__global__ void gx_kernel(const float* __restrict__ gW1, const float* __restrict__ gb1,
                          const float* __restrict__ gW2, const float* __restrict__ gb2,
                          const float* __restrict__ gW3, const float* __restrict__ gb3) {
    int b = blockIdx.x, tid = threadIdx.x;
    __shared__ float sh[HH], s1[HGG], s2[HGG];
    for (int k = tid; k < HH; k += blockDim.x) sh[k] = g_hB[b * HH + k];
    __syncthreads();
    if (tid < HGG) {
        float a = __ldg(gb1 + tid);
        const float* w = gW1 + tid * HH;
        for (int k = 0; k < HH; k++) a = fmaf(__ldg(w + k), sh[k], a);
        s1[tid] = leaky1(a);
    }
    __syncthreads();
    if (tid < HGG) {
        float a = __ldg(gb2 + tid);
        const float* w = gW2 + tid * HGG;
        for (int k = 0; k < HGG; k++) a = fmaf(__ldg(w + k), s1[k], a);
        s2[tid] = leaky1(a);
    }
    __syncthreads();
    if (tid < 2) {
        float a = __ldg(gb3 + tid);
        const float* w = gW3 + tid * HGG;
        for (int k = 0; k < HGG; k++) a = fmaf(__ldg(w + k), s2[k], a);
        g_gx[b * 2 + tid] = a;
    }
}

__global__ void z0_kernel(const float* __restrict__ eps) {
    int b = blockIdx.x, h = threadIdx.x;
    float loc, scale;
    if (b < NB / 2) {
        loc   = g_gx[(2 * b) * 2 + 0];
        scale = g_gx[(2 * b + 1) * 2 + 0];
    } else {
        int i = 2 * (b - NB / 2);
        loc   = fabsf(g_gx[i * 2 + 1]);
        scale = fabsf(g_gx[(i + 1) * 2 + 1]);
    }
    g_z0[b * HH + h] = loc + scale * eps[h * NB + b];
}

// ---- rollout output MLP, single row ----
__device__ __forceinline__ void out_mlp(int tid, float* sm, int r, int s,
        float rob1, float rob2,
        const float* __restrict__ oW3, const float* __restrict__ ob3,
        float* __restrict__ out) {
    float* ha = sm + BUF_HA;   // o1
    float* P  = sm + BUF_P;    // o2
    float* s_y = sm + BUF_Y;
    if (tid < HOO) {
        const float4* y4 = (const float4*)s_y;
        float a0 = rob1, a1 = 0.f, b0 = 0.f, b1 = 0.f;
#pragma unroll
        for (int k = 0; k < 100; k += 4) {
            float w0 = __ldcg(g_oW1T + k * 75 + tid);
            float w1 = __ldcg(g_oW1T + (k + 1) * 75 + tid);
            float w2 = __ldcg(g_oW1T + (k + 2) * 75 + tid);
            float w3 = __ldcg(g_oW1T + (k + 3) * 75 + tid);
            float4 y = y4[k >> 2];
            a0 = fmaf(w0, y.x, a0); a1 = fmaf(w1, y.y, a1);
            b0 = fmaf(w2, y.z, b0); b1 = fmaf(w3, y.w, b1);
        }
        ha[tid] = leaky1((a0 + a1) + (b0 + b1));
    }
    __syncthreads();
    if (tid < HOO) {
        float a0 = rob2, a1 = 0.f;
#pragma unroll
        for (int k = 0; k < 74; k += 2) {
            float w0 = __ldcg(g_oW2T + k * 75 + tid);
            float w1 = __ldcg(g_oW2T + (k + 1) * 75 + tid);
            a0 = fmaf(w0, ha[k], a0);
            a1 = fmaf(w1, ha[k + 1], a1);
        }
        a0 = fmaf(__ldcg(g_oW2T + 74 * 75 + tid), ha[74], a0);
        P[tid] = leaky1(a0 + a1);
    }
    __syncthreads();
    if (tid < 32) {
        float a0 = 0.f;
        for (int k = tid; k < HOO; k += 32)
            a0 = fmaf(__ldg(oW3 + k), P[k], a0);
#pragma unroll
        for (int o = 16; o; o >>= 1)
            a0 += __shfl_down_sync(0xffffffffu, a0, o);
        if (tid == 0) out[r * TFUT + s] = a0 + __ldg(ob3);
    }
    __syncthreads();
}

__global__ void __launch_bounds__(NTHR, 2) rollout_kernel(
        const float* __restrict__ tf_,
        const float* __restrict__ fb1, const float* __restrict__ fb2,
        const float* __restrict__ fb3,
        const float* __restrict__ ob1, const float* __restrict__ ob2,
        const float* __restrict__ oW3, const float* __restrict__ ob3,
        float* __restrict__ out) {
    extern __shared__ float sm[];
    int tid = threadIdx.x;
    int r = blockIdx.x;

    load_shared_weights(tid, sm);

    float rb1 = (tid < NF) ? __ldg(fb1 + tid) : 0.f;
    float rb2a = 0.f, rb2b = 0.f;
    if (tid < 138) {
        rb2a = __ldg(fb2 + 2 * tid);
        rb2b = (2 * tid + 1 < NF) ? __ldg(fb2 + 2 * tid + 1) : 0.f;
    }
    float rb3 = (tid < HH) ? __ldg(fb3 + tid) : 0.f;
    float rob1 = (tid < HOO) ? __ldg(ob1 + tid) : 0.f;
    float rob2 = (tid < HOO) ? __ldg(ob2 + tid) : 0.f;

    float* s_y = sm + BUF_Y;
    if (tid < HH) s_y[tid] = g_z0[r * HH + tid];
    __syncthreads();

    out_mlp(tid, sm, r, 0, rob1, rob2, oW3, ob3, out);

    float tprev = tf_[r * TFUT];
    for (int s = 1; s < TFUT; s++) {
        float tcur = tf_[r * TFUT + s];
        integrate2(tid, sm, tprev, tcur, rb1, rb2a, rb2b, rb3);
        out_mlp(tid, sm, r, s, rob1, rob2, oW3, ob3, out);
        tprev = tcur;
    }
}

extern "C" void kernel_launch(void* const* d_in, const int* in_sizes, int n_in,
                              void* d_out, int out_size) {
    const float* past = (const float*)d_in[0];
    const float* h0   = (const float*)d_in[1];
    const float* t_fu = (const float*)d_in[2];
    const float* eps  = (const float*)d_in[3];
    const float* fW1  = (const float*)d_in[4];
    const float* fb1  = (const float*)d_in[5];
    const float* fW2  = (const float*)d_in[6];
    const float* fb2  = (const float*)d_in[7];
    const float* fW3  = (const float*)d_in[8];
    const float* fb3  = (const float*)d_in[9];
    const float* Wih  = (const float*)d_in[10];
    const float* Whh  = (const float*)d_in[11];
    const float* bih  = (const float*)d_in[12];
    const float* bhh  = (const float*)d_in[13];
    const float* gW1  = (const float*)d_in[14];
    const float* gb1  = (const float*)d_in[15];
    const float* gW2  = (const float*)d_in[16];
    const float* gb2  = (const float*)d_in[17];
    const float* gW3  = (const float*)d_in[18];
    const float* gb3  = (const float*)d_in[19];
    const float* oW1  = (const float*)d_in[20];
    const float* ob1  = (const float*)d_in[21];
    const float* oW2  = (const float*)d_in[22];
    const float* ob2  = (const float*)d_in[23];
    const float* oW3  = (const float*)d_in[24];
    const float* ob3  = (const float*)d_in[25];
    float* out = (float*)d_out;

    static bool attr_done = false;
    if (!attr_done) {
        cudaFuncSetAttribute(encode_kernel,
                             cudaFuncAttributeMaxDynamicSharedMemorySize, SMEM_BYTES);
        cudaFuncSetAttribute(rollout_kernel,
                             cudaFuncAttributeMaxDynamicSharedMemorySize, SMEM_BYTES);
        attr_done = true;
    }

    prep_kernel<<<192, 256>>>(fW1, fW2, fW3, Whh, oW1, oW2);
    encode_kernel<<<NCTA, NTHR, SMEM_BYTES>>>(past, h0, fb1, fb2, fb3, Wih, bih, bhh);
    gx_kernel<<<NB, 96>>>(gW1, gb1, gW2, gb2, gW3, gb3);
    z0_kernel<<<NB, HH>>>(eps);
    rollout_kernel<<<NCTA, NTHR, SMEM_BYTES>>>(t_fu, fb1, fb2, fb3,
                                               ob1, ob2, oW3, ob3, out);
}